// round 1
// baseline (speedup 1.0000x reference)
#include <cuda_runtime.h>
#include <math.h>

// ---------------------------------------------------------------------------
// Round 0: fully fp32 SIMT baseline.
// Pipeline (M=B*S=8192, D=2048, F=8192):
//   1) up    = x @ w_up^T          (NT)  -> bufA
//   2) gate  = x @ w_gate^T        (NT)  -> bufB
//   3) up2   = bufA @ h_up_T       (NN)  -> bufC
//   4) gated = bufC * silu(bufB @ h_gate_T)   (NN + fused SwiGLU epi) -> bufA
//   5) g3    = bufA @ h_down       (NN)  -> bufC
//   6) out   = bufC @ w_down^T     (NT)  -> d_out
// All dims are multiples of the tile sizes for this problem; no bounds checks.
// ---------------------------------------------------------------------------

#define BM 128
#define BN 128
#define BK 8
#define TM 8
#define TN 8
#define NTHREADS 256

// Scratch: 3 x 8192*8192 fp32 = 3 x 256 MB (static device arrays; no allocs).
__device__ float g_bufA[67108864];
__device__ float g_bufB[67108864];
__device__ float g_bufC[67108864];

// BT = true  : B is [N,K] row-major, compute C = A * B^T   (NT)
// BT = false : B is [K,N] row-major, compute C = A * B     (NN)
// EPI = 0 : C = acc
// EPI = 1 : C = OTH * silu(acc)    (SwiGLU fusion; OTH same [M,N] layout)
template <bool BT, int EPI>
__global__ __launch_bounds__(NTHREADS, 2)
void sgemm128(const float* __restrict__ A, const float* __restrict__ B,
              float* __restrict__ C, const float* __restrict__ OTH,
              int M, int N, int K)
{
    __shared__ float As[2][BK][BM];
    __shared__ float Bs[2][BK][BN];

    const int tid = threadIdx.x;
    const int bm  = blockIdx.y * BM;
    const int bn  = blockIdx.x * BN;

    const int tx = tid & 15;   // 0..15 -> N direction
    const int ty = tid >> 4;   // 0..15 -> M direction

    // ---- global-load addressing --------------------------------------------
    // A tile: 128 rows x 8 k, one float4 per thread, stored transposed to As.
    const int arow = tid >> 1;            // 0..127
    const int acol = (tid & 1) * 4;       // 0 or 4
    const float* Aptr = A + (size_t)(bm + arow) * K + acol;

    const float* Bptr;
    int brow, bcol;
    if (BT) {
        brow = tid >> 1;                  // 0..127 (N rows)
        bcol = (tid & 1) * 4;             // k
        Bptr = B + (size_t)(bn + brow) * K + bcol;
    } else {
        brow = tid >> 5;                  // 0..7   (k rows)
        bcol = (tid & 31) * 4;            // 0..124 (N)
        Bptr = B + (size_t)brow * N + bn + bcol;
    }

    float acc[TM][TN];
#pragma unroll
    for (int i = 0; i < TM; i++)
#pragma unroll
        for (int j = 0; j < TN; j++) acc[i][j] = 0.0f;

    const int nk = K / BK;

    // ---- prologue: load tile 0 ---------------------------------------------
    {
        float4 a = *(const float4*)(Aptr);
        As[0][acol + 0][arow] = a.x;
        As[0][acol + 1][arow] = a.y;
        As[0][acol + 2][arow] = a.z;
        As[0][acol + 3][arow] = a.w;
        if (BT) {
            float4 b = *(const float4*)(Bptr);
            Bs[0][bcol + 0][brow] = b.x;
            Bs[0][bcol + 1][brow] = b.y;
            Bs[0][bcol + 2][brow] = b.z;
            Bs[0][bcol + 3][brow] = b.w;
        } else {
            *(float4*)&Bs[0][brow][bcol] = *(const float4*)(Bptr);
        }
    }
    __syncthreads();

    // ---- main loop: smem double-buffer, global prefetch into registers -----
    for (int t = 0; t < nk; t++) {
        const int cur = t & 1;
        const int nxt = cur ^ 1;

        float4 na, nb;
        const bool more = (t + 1 < nk);
        if (more) {
            na = *(const float4*)(Aptr + (size_t)(t + 1) * BK);
            if (BT) nb = *(const float4*)(Bptr + (size_t)(t + 1) * BK);
            else    nb = *(const float4*)(Bptr + (size_t)(t + 1) * BK * N);
        }

#pragma unroll
        for (int kk = 0; kk < BK; kk++) {
            float ra[TM], rb[TN];
            *(float4*)&ra[0] = *(const float4*)&As[cur][kk][ty * TM];
            *(float4*)&ra[4] = *(const float4*)&As[cur][kk][ty * TM + 4];
            *(float4*)&rb[0] = *(const float4*)&Bs[cur][kk][tx * TN];
            *(float4*)&rb[4] = *(const float4*)&Bs[cur][kk][tx * TN + 4];
#pragma unroll
            for (int i = 0; i < TM; i++)
#pragma unroll
                for (int j = 0; j < TN; j++)
                    acc[i][j] = fmaf(ra[i], rb[j], acc[i][j]);
        }

        if (more) {
            As[nxt][acol + 0][arow] = na.x;
            As[nxt][acol + 1][arow] = na.y;
            As[nxt][acol + 2][arow] = na.z;
            As[nxt][acol + 3][arow] = na.w;
            if (BT) {
                Bs[nxt][bcol + 0][brow] = nb.x;
                Bs[nxt][bcol + 1][brow] = nb.y;
                Bs[nxt][bcol + 2][brow] = nb.z;
                Bs[nxt][bcol + 3][brow] = nb.w;
            } else {
                *(float4*)&Bs[nxt][brow][bcol] = nb;
            }
        }
        __syncthreads();
    }

    // ---- epilogue ------------------------------------------------------------
    const int row0 = bm + ty * TM;
    const int col0 = bn + tx * TN;
#pragma unroll
    for (int i = 0; i < TM; i++) {
        const size_t base = (size_t)(row0 + i) * N + col0;
#pragma unroll
        for (int j = 0; j < TN; j += 4) {
            float4 v;
            v.x = acc[i][j + 0];
            v.y = acc[i][j + 1];
            v.z = acc[i][j + 2];
            v.w = acc[i][j + 3];
            if (EPI == 1) {
                float4 u = *(const float4*)(OTH + base + j);
                v.x = u.x * (v.x / (1.0f + expf(-v.x)));
                v.y = u.y * (v.y / (1.0f + expf(-v.y)));
                v.z = u.z * (v.z / (1.0f + expf(-v.z)));
                v.w = u.w * (v.w / (1.0f + expf(-v.w)));
            }
            *(float4*)(C + base + j) = v;
        }
    }
}

extern "C" void kernel_launch(void* const* d_in, const int* in_sizes, int n_in,
                              void* d_out, int out_size)
{
    const float* x      = (const float*)d_in[0];
    const float* w_up   = (const float*)d_in[1];
    const float* w_gate = (const float*)d_in[2];
    const float* w_down = (const float*)d_in[3];
    const float* h_up   = (const float*)d_in[4];
    const float* h_gate = (const float*)d_in[5];
    const float* h_down = (const float*)d_in[6];

    // Derive dims: h_up_T is [F,F]; w_up is [F,D]; x is [M,D].
    int F = 1;
    while ((long long)(F + 1) * (F + 1) <= (long long)in_sizes[4]) F++;
    const int D = in_sizes[1] / F;
    const int M = in_sizes[0] / D;

    float *bufA, *bufB, *bufC;
    cudaGetSymbolAddress((void**)&bufA, g_bufA);
    cudaGetSymbolAddress((void**)&bufB, g_bufB);
    cudaGetSymbolAddress((void**)&bufC, g_bufC);

    const dim3 blk(NTHREADS);
    const dim3 gMF(F / BN, M / BM);
    const dim3 gMD(D / BN, M / BM);

    // 1) up = x @ w_up^T
    sgemm128<true, 0><<<gMF, blk>>>(x, w_up, bufA, nullptr, M, F, D);
    // 2) gate = x @ w_gate^T
    sgemm128<true, 0><<<gMF, blk>>>(x, w_gate, bufB, nullptr, M, F, D);
    // 3) up2 = up @ h_up_T
    sgemm128<false, 0><<<gMF, blk>>>(bufA, h_up, bufC, nullptr, M, F, F);
    // 4) gated = up2 * silu(gate @ h_gate_T)
    sgemm128<false, 1><<<gMF, blk>>>(bufB, h_gate, bufA, bufC, M, F, F);
    // 5) g3 = gated @ h_down
    sgemm128<false, 0><<<gMF, blk>>>(bufA, h_down, bufC, nullptr, M, F, F);
    // 6) out = g3 @ w_down^T
    sgemm128<true, 0><<<gMD, blk>>>(bufC, w_down, (float*)d_out, nullptr, M, D, F);
}

// round 2
// speedup vs baseline: 1.0020x; 1.0020x over previous
#include <cuda_runtime.h>
#include <math.h>

// ---------------------------------------------------------------------------
// Round 0: fully fp32 SIMT baseline.
// Pipeline (M=B*S=8192, D=2048, F=8192):
//   1) up    = x @ w_up^T          (NT)  -> bufA
//   2) gate  = x @ w_gate^T        (NT)  -> bufB
//   3) up2   = bufA @ h_up_T       (NN)  -> bufC
//   4) gated = bufC * silu(bufB @ h_gate_T)   (NN + fused SwiGLU epi) -> bufA
//   5) g3    = bufA @ h_down       (NN)  -> bufC
//   6) out   = bufC @ w_down^T     (NT)  -> d_out
// All dims are multiples of the tile sizes for this problem; no bounds checks.
// ---------------------------------------------------------------------------

#define BM 128
#define BN 128
#define BK 8
#define TM 8
#define TN 8
#define NTHREADS 256

// Scratch: 3 x 8192*8192 fp32 = 3 x 256 MB (static device arrays; no allocs).
__device__ float g_bufA[67108864];
__device__ float g_bufB[67108864];
__device__ float g_bufC[67108864];

// BT = true  : B is [N,K] row-major, compute C = A * B^T   (NT)
// BT = false : B is [K,N] row-major, compute C = A * B     (NN)
// EPI = 0 : C = acc
// EPI = 1 : C = OTH * silu(acc)    (SwiGLU fusion; OTH same [M,N] layout)
template <bool BT, int EPI>
__global__ __launch_bounds__(NTHREADS, 2)
void sgemm128(const float* __restrict__ A, const float* __restrict__ B,
              float* __restrict__ C, const float* __restrict__ OTH,
              int M, int N, int K)
{
    __shared__ float As[2][BK][BM];
    __shared__ float Bs[2][BK][BN];

    const int tid = threadIdx.x;
    const int bm  = blockIdx.y * BM;
    const int bn  = blockIdx.x * BN;

    const int tx = tid & 15;   // 0..15 -> N direction
    const int ty = tid >> 4;   // 0..15 -> M direction

    // ---- global-load addressing --------------------------------------------
    // A tile: 128 rows x 8 k, one float4 per thread, stored transposed to As.
    const int arow = tid >> 1;            // 0..127
    const int acol = (tid & 1) * 4;       // 0 or 4
    const float* Aptr = A + (size_t)(bm + arow) * K + acol;

    const float* Bptr;
    int brow, bcol;
    if (BT) {
        brow = tid >> 1;                  // 0..127 (N rows)
        bcol = (tid & 1) * 4;             // k
        Bptr = B + (size_t)(bn + brow) * K + bcol;
    } else {
        brow = tid >> 5;                  // 0..7   (k rows)
        bcol = (tid & 31) * 4;            // 0..124 (N)
        Bptr = B + (size_t)brow * N + bn + bcol;
    }

    float acc[TM][TN];
#pragma unroll
    for (int i = 0; i < TM; i++)
#pragma unroll
        for (int j = 0; j < TN; j++) acc[i][j] = 0.0f;

    const int nk = K / BK;

    // ---- prologue: load tile 0 ---------------------------------------------
    {
        float4 a = *(const float4*)(Aptr);
        As[0][acol + 0][arow] = a.x;
        As[0][acol + 1][arow] = a.y;
        As[0][acol + 2][arow] = a.z;
        As[0][acol + 3][arow] = a.w;
        if (BT) {
            float4 b = *(const float4*)(Bptr);
            Bs[0][bcol + 0][brow] = b.x;
            Bs[0][bcol + 1][brow] = b.y;
            Bs[0][bcol + 2][brow] = b.z;
            Bs[0][bcol + 3][brow] = b.w;
        } else {
            *(float4*)&Bs[0][brow][bcol] = *(const float4*)(Bptr);
        }
    }
    __syncthreads();

    // ---- main loop: smem double-buffer, global prefetch into registers -----
    for (int t = 0; t < nk; t++) {
        const int cur = t & 1;
        const int nxt = cur ^ 1;

        float4 na, nb;
        const bool more = (t + 1 < nk);
        if (more) {
            na = *(const float4*)(Aptr + (size_t)(t + 1) * BK);
            if (BT) nb = *(const float4*)(Bptr + (size_t)(t + 1) * BK);
            else    nb = *(const float4*)(Bptr + (size_t)(t + 1) * BK * N);
        }

#pragma unroll
        for (int kk = 0; kk < BK; kk++) {
            float ra[TM], rb[TN];
            *(float4*)&ra[0] = *(const float4*)&As[cur][kk][ty * TM];
            *(float4*)&ra[4] = *(const float4*)&As[cur][kk][ty * TM + 4];
            *(float4*)&rb[0] = *(const float4*)&Bs[cur][kk][tx * TN];
            *(float4*)&rb[4] = *(const float4*)&Bs[cur][kk][tx * TN + 4];
#pragma unroll
            for (int i = 0; i < TM; i++)
#pragma unroll
                for (int j = 0; j < TN; j++)
                    acc[i][j] = fmaf(ra[i], rb[j], acc[i][j]);
        }

        if (more) {
            As[nxt][acol + 0][arow] = na.x;
            As[nxt][acol + 1][arow] = na.y;
            As[nxt][acol + 2][arow] = na.z;
            As[nxt][acol + 3][arow] = na.w;
            if (BT) {
                Bs[nxt][bcol + 0][brow] = nb.x;
                Bs[nxt][bcol + 1][brow] = nb.y;
                Bs[nxt][bcol + 2][brow] = nb.z;
                Bs[nxt][bcol + 3][brow] = nb.w;
            } else {
                *(float4*)&Bs[nxt][brow][bcol] = nb;
            }
        }
        __syncthreads();
    }

    // ---- epilogue ------------------------------------------------------------
    const int row0 = bm + ty * TM;
    const int col0 = bn + tx * TN;
#pragma unroll
    for (int i = 0; i < TM; i++) {
        const size_t base = (size_t)(row0 + i) * N + col0;
#pragma unroll
        for (int j = 0; j < TN; j += 4) {
            float4 v;
            v.x = acc[i][j + 0];
            v.y = acc[i][j + 1];
            v.z = acc[i][j + 2];
            v.w = acc[i][j + 3];
            if (EPI == 1) {
                float4 u = *(const float4*)(OTH + base + j);
                v.x = u.x * (v.x / (1.0f + expf(-v.x)));
                v.y = u.y * (v.y / (1.0f + expf(-v.y)));
                v.z = u.z * (v.z / (1.0f + expf(-v.z)));
                v.w = u.w * (v.w / (1.0f + expf(-v.w)));
            }
            *(float4*)(C + base + j) = v;
        }
    }
}

extern "C" void kernel_launch(void* const* d_in, const int* in_sizes, int n_in,
                              void* d_out, int out_size)
{
    const float* x      = (const float*)d_in[0];
    const float* w_up   = (const float*)d_in[1];
    const float* w_gate = (const float*)d_in[2];
    const float* w_down = (const float*)d_in[3];
    const float* h_up   = (const float*)d_in[4];
    const float* h_gate = (const float*)d_in[5];
    const float* h_down = (const float*)d_in[6];

    // Derive dims: h_up_T is [F,F]; w_up is [F,D]; x is [M,D].
    int F = 1;
    while ((long long)(F + 1) * (F + 1) <= (long long)in_sizes[4]) F++;
    const int D = in_sizes[1] / F;
    const int M = in_sizes[0] / D;

    float *bufA, *bufB, *bufC;
    cudaGetSymbolAddress((void**)&bufA, g_bufA);
    cudaGetSymbolAddress((void**)&bufB, g_bufB);
    cudaGetSymbolAddress((void**)&bufC, g_bufC);

    const dim3 blk(NTHREADS);
    const dim3 gMF(F / BN, M / BM);
    const dim3 gMD(D / BN, M / BM);

    // 1) up = x @ w_up^T
    sgemm128<true, 0><<<gMF, blk>>>(x, w_up, bufA, nullptr, M, F, D);
    // 2) gate = x @ w_gate^T
    sgemm128<true, 0><<<gMF, blk>>>(x, w_gate, bufB, nullptr, M, F, D);
    // 3) up2 = up @ h_up_T
    sgemm128<false, 0><<<gMF, blk>>>(bufA, h_up, bufC, nullptr, M, F, F);
    // 4) gated = up2 * silu(gate @ h_gate_T)
    sgemm128<false, 1><<<gMF, blk>>>(bufB, h_gate, bufA, bufC, M, F, F);
    // 5) g3 = gated @ h_down
    sgemm128<false, 0><<<gMF, blk>>>(bufA, h_down, bufC, nullptr, M, F, F);
    // 6) out = g3 @ w_down^T
    sgemm128<true, 0><<<gMD, blk>>>(bufC, w_down, (float*)d_out, nullptr, M, D, F);
}

// round 4
// speedup vs baseline: 3.1800x; 3.1737x over previous
#include <cuda_runtime.h>
#include <cuda_bf16.h>
#include <math.h>
#include <stdint.h>

// ===========================================================================
// bf16x3 split GEMM via legacy mma.sync (compute_103-safe: no tcgen05).
// C[M,N] = A[M,K] @ B[N,K]^T with A,B pre-split into (bf16 hi, bf16 lo).
// acc = Ah*Bh + Ah*Bl + Al*Bh  (fp32 accumulators)  ~1e-5 per-GEMM rel err.
// ===========================================================================

#define TILE_B 8192              // one 128x32 bf16 tile in smem (bytes)
#define STAGE_B 32768            // 4 tiles (Ah,Al,Bh,Bl)
#define SMEM_B3 98304            // 3 stages

__device__ __forceinline__ uint32_t smem_u32(const void* p) {
    uint32_t a;
    asm("{ .reg .u64 t; cvta.to.shared.u64 t, %1; cvt.u32.u64 %0, t; }" : "=r"(a) : "l"(p));
    return a;
}
__device__ __forceinline__ void cp16(uint32_t s, const void* g) {
    asm volatile("cp.async.cg.shared.global [%0], [%1], 16;" :: "r"(s), "l"(g));
}
#define CP_COMMIT() asm volatile("cp.async.commit_group;" ::: "memory")
#define CP_WAIT1()  asm volatile("cp.async.wait_group 1;" ::: "memory")
#define LDSM4(R, a) \
    asm volatile("ldmatrix.sync.aligned.m8n8.x4.shared.b16 {%0,%1,%2,%3}, [%4];" \
        : "=r"((R)[0]), "=r"((R)[1]), "=r"((R)[2]), "=r"((R)[3]) : "r"(a))

__device__ __forceinline__ void mma_bf16(float* c, const uint32_t* a, uint32_t b0, uint32_t b1) {
    asm volatile(
        "mma.sync.aligned.m16n8k16.row.col.f32.bf16.bf16.f32 "
        "{%0,%1,%2,%3}, {%4,%5,%6,%7}, {%8,%9}, {%0,%1,%2,%3};"
        : "+f"(c[0]), "+f"(c[1]), "+f"(c[2]), "+f"(c[3])
        : "r"(a[0]), "r"(a[1]), "r"(a[2]), "r"(a[3]), "r"(b0), "r"(b1));
}

// 16B-granular XOR swizzle: (row, col16) -> byte offset within a 128x32 tile.
__device__ __forceinline__ uint32_t sw(int row, int col16) {
    return (uint32_t)(row * 64 + ((col16 ^ ((row >> 1) & 3)) << 4));
}

// load one pipeline stage: 4 tiles, 2 x 16B chunks per thread per tile
__device__ __forceinline__ void ld_stage(
    uint32_t sb, int buf, int t,
    const __nv_bfloat16* __restrict__ Ah, const __nv_bfloat16* __restrict__ Al,
    const __nv_bfloat16* __restrict__ Bh, const __nv_bfloat16* __restrict__ Bl,
    int bm, int bn, int K, int tid)
{
    const int k0 = t * 32;
    const uint32_t stb = sb + (uint32_t)buf * STAGE_B;
#pragma unroll
    for (int i = 0; i < 2; i++) {
        const int c = tid + i * 256;
        const int row = c >> 2, col16 = c & 3;
        const size_t gA = (size_t)(bm + row) * K + k0 + col16 * 8;
        const size_t gB = (size_t)(bn + row) * K + k0 + col16 * 8;
        const uint32_t so = stb + sw(row, col16);
        cp16(so,              Ah + gA);
        cp16(so + TILE_B,     Al + gA);
        cp16(so + 2 * TILE_B, Bh + gB);
        cp16(so + 3 * TILE_B, Bl + gB);
    }
}

// EPI 0: split-write (Ch,Cl bf16).  EPI 1: fp32 write Cf.
// EPI 2: v = OTH * silu(acc), split-write.
template <int EPI>
__global__ __launch_bounds__(256) void gemm_b3(
    const __nv_bfloat16* __restrict__ Ah, const __nv_bfloat16* __restrict__ Al,
    const __nv_bfloat16* __restrict__ Bh, const __nv_bfloat16* __restrict__ Bl,
    float* __restrict__ Cf, __nv_bfloat16* __restrict__ Ch, __nv_bfloat16* __restrict__ Cl,
    const float* __restrict__ OTH, int M, int N, int K)
{
    extern __shared__ char smem[];
    const uint32_t sb = smem_u32(smem);
    const int tid = threadIdx.x;
    const int bm = blockIdx.y * 128, bn = blockIdx.x * 128;
    const int w = tid >> 5, lane = tid & 31;
    const int wm = (w >> 2) * 64, wn = (w & 3) * 32;
    const int jj = lane >> 3, rr = lane & 7;
    const int aR = (jj & 1) * 8 + rr, aC16 = jj >> 1;   // A: (m0k0)(m8k0)(m0k8)(m8k8)
    const int bR = (jj >> 1) * 8 + rr, bC16 = jj & 1;   // B: (n0k0)(n0k8)(n8k0)(n8k8)

    float c[4][4][4];
#pragma unroll
    for (int mi = 0; mi < 4; mi++)
#pragma unroll
        for (int ni = 0; ni < 4; ni++)
#pragma unroll
            for (int q = 0; q < 4; q++) c[mi][ni][q] = 0.0f;

    const int nst = K / 32;
    ld_stage(sb, 0, 0, Ah, Al, Bh, Bl, bm, bn, K, tid); CP_COMMIT();
    ld_stage(sb, 1, 1, Ah, Al, Bh, Bl, bm, bn, K, tid); CP_COMMIT();

    for (int t = 0; t < nst; t++) {
        CP_WAIT1();
        __syncthreads();
        if (t + 2 < nst)
            ld_stage(sb, (t + 2) % 3, t + 2, Ah, Al, Bh, Bl, bm, bn, K, tid);
        CP_COMMIT();

        const uint32_t stb = sb + (uint32_t)((t % 3) * STAGE_B);
#pragma unroll
        for (int ks = 0; ks < 2; ks++) {
            uint32_t ah[4][4], al[4][4], bh[2][4], bl[2][4];
#pragma unroll
            for (int mi = 0; mi < 4; mi++) {
                const int row = wm + mi * 16 + aR;
                const uint32_t ad = stb + sw(row, ks * 2 + aC16);
                LDSM4(ah[mi], ad);
                LDSM4(al[mi], ad + TILE_B);
            }
#pragma unroll
            for (int np = 0; np < 2; np++) {
                const int row = wn + np * 16 + bR;
                const uint32_t bd = stb + 2 * TILE_B + sw(row, ks * 2 + bC16);
                LDSM4(bh[np], bd);
                LDSM4(bl[np], bd + TILE_B);
            }
#pragma unroll
            for (int mi = 0; mi < 4; mi++)
#pragma unroll
                for (int ni = 0; ni < 4; ni++) {
                    const uint32_t b0h = bh[ni >> 1][(ni & 1) * 2];
                    const uint32_t b1h = bh[ni >> 1][(ni & 1) * 2 + 1];
                    const uint32_t b0l = bl[ni >> 1][(ni & 1) * 2];
                    const uint32_t b1l = bl[ni >> 1][(ni & 1) * 2 + 1];
                    mma_bf16(c[mi][ni], ah[mi], b0h, b1h);
                    mma_bf16(c[mi][ni], ah[mi], b0l, b1l);
                    mma_bf16(c[mi][ni], al[mi], b0h, b1h);
                }
        }
    }

    // ---- epilogue ----
#pragma unroll
    for (int mi = 0; mi < 4; mi++)
#pragma unroll
        for (int ni = 0; ni < 4; ni++) {
            const int r0 = bm + wm + mi * 16 + (lane >> 2);
            const int col = bn + wn + ni * 8 + (lane & 3) * 2;
            const size_t o0 = (size_t)r0 * N + col;
            const size_t o1 = (size_t)(r0 + 8) * N + col;
            float v0 = c[mi][ni][0], v1 = c[mi][ni][1];
            float v2 = c[mi][ni][2], v3 = c[mi][ni][3];
            if (EPI == 2) {
                const float2 u0 = *(const float2*)(OTH + o0);
                const float2 u1 = *(const float2*)(OTH + o1);
                v0 = u0.x * (v0 / (1.0f + expf(-v0)));
                v1 = u0.y * (v1 / (1.0f + expf(-v1)));
                v2 = u1.x * (v2 / (1.0f + expf(-v2)));
                v3 = u1.y * (v3 / (1.0f + expf(-v3)));
            }
            if (EPI == 1) {
                *(float2*)(Cf + o0) = make_float2(v0, v1);
                *(float2*)(Cf + o1) = make_float2(v2, v3);
            } else {
                __nv_bfloat162 hh, ll;
                hh.x = __float2bfloat16(v0); hh.y = __float2bfloat16(v1);
                ll.x = __float2bfloat16(v0 - __bfloat162float(hh.x));
                ll.y = __float2bfloat16(v1 - __bfloat162float(hh.y));
                *(__nv_bfloat162*)(Ch + o0) = hh;
                *(__nv_bfloat162*)(Cl + o0) = ll;
                hh.x = __float2bfloat16(v2); hh.y = __float2bfloat16(v3);
                ll.x = __float2bfloat16(v2 - __bfloat162float(hh.x));
                ll.y = __float2bfloat16(v3 - __bfloat162float(hh.y));
                *(__nv_bfloat162*)(Ch + o1) = hh;
                *(__nv_bfloat162*)(Cl + o1) = ll;
            }
        }
}

// ===========================================================================
// scratch (static; no allocations). bf16 slab 768M elems + fp32 C1.
// ===========================================================================
#define MDE 16777216ll
#define FFE 67108864ll
__device__ __nv_bfloat16 g_bf[805306368];
__device__ float g_c1[67108864];

// ---- pre-pass: fp32 -> (bf16 hi, bf16 lo) ----
struct bf4 { __nv_bfloat162 a, b; };
__global__ void split_k(const float4* __restrict__ in, bf4* __restrict__ hi,
                        bf4* __restrict__ lo, int n4) {
    for (int i = blockIdx.x * blockDim.x + threadIdx.x; i < n4; i += gridDim.x * blockDim.x) {
        const float4 v = in[i];
        bf4 H, L;
        H.a.x = __float2bfloat16(v.x); H.a.y = __float2bfloat16(v.y);
        H.b.x = __float2bfloat16(v.z); H.b.y = __float2bfloat16(v.w);
        L.a.x = __float2bfloat16(v.x - __bfloat162float(H.a.x));
        L.a.y = __float2bfloat16(v.y - __bfloat162float(H.a.y));
        L.b.x = __float2bfloat16(v.z - __bfloat162float(H.b.x));
        L.b.y = __float2bfloat16(v.w - __bfloat162float(H.b.y));
        hi[i] = H; lo[i] = L;
    }
}
// transpose + split: out_{hi,lo}[n*F+k] = split(in[k*F+n])
__global__ void tsplit_k(const float* __restrict__ in, __nv_bfloat16* __restrict__ hi,
                         __nv_bfloat16* __restrict__ lo, int F) {
    __shared__ float t[32][33];
    const int c0 = blockIdx.x * 32, r0 = blockIdx.y * 32;
#pragma unroll
    for (int i = 0; i < 32; i += 8)
        t[threadIdx.y + i][threadIdx.x] = in[(size_t)(r0 + threadIdx.y + i) * F + c0 + threadIdx.x];
    __syncthreads();
#pragma unroll
    for (int i = 0; i < 32; i += 8) {
        const float v = t[threadIdx.x][threadIdx.y + i];
        const __nv_bfloat16 h = __float2bfloat16(v);
        const size_t o = (size_t)(c0 + threadIdx.y + i) * F + r0 + threadIdx.x;
        hi[o] = h;
        lo[o] = __float2bfloat16(v - __bfloat162float(h));
    }
}

// ===========================================================================
static void rung(int epi,
                 const __nv_bfloat16* Ah, const __nv_bfloat16* Al,
                 const __nv_bfloat16* Bh, const __nv_bfloat16* Bl,
                 float* Cf, __nv_bfloat16* Ch, __nv_bfloat16* Cl,
                 const float* OTH, int M, int N, int K)
{
    const dim3 g(N / 128, M / 128), b(256);
    if (epi == 0) {
        cudaFuncSetAttribute(gemm_b3<0>, cudaFuncAttributeMaxDynamicSharedMemorySize, SMEM_B3);
        gemm_b3<0><<<g, b, SMEM_B3>>>(Ah, Al, Bh, Bl, Cf, Ch, Cl, OTH, M, N, K);
    } else if (epi == 1) {
        cudaFuncSetAttribute(gemm_b3<1>, cudaFuncAttributeMaxDynamicSharedMemorySize, SMEM_B3);
        gemm_b3<1><<<g, b, SMEM_B3>>>(Ah, Al, Bh, Bl, Cf, Ch, Cl, OTH, M, N, K);
    } else {
        cudaFuncSetAttribute(gemm_b3<2>, cudaFuncAttributeMaxDynamicSharedMemorySize, SMEM_B3);
        gemm_b3<2><<<g, b, SMEM_B3>>>(Ah, Al, Bh, Bl, Cf, Ch, Cl, OTH, M, N, K);
    }
}

extern "C" void kernel_launch(void* const* d_in, const int* in_sizes, int n_in,
                              void* d_out, int out_size)
{
    const float* x  = (const float*)d_in[0];
    const float* wu = (const float*)d_in[1];
    const float* wg = (const float*)d_in[2];
    const float* wd = (const float*)d_in[3];
    const float* h1 = (const float*)d_in[4];
    const float* h2 = (const float*)d_in[5];
    const float* h3 = (const float*)d_in[6];

    int F = 1;
    while ((long long)(F + 1) * (F + 1) <= (long long)in_sizes[4]) F++;
    const int D = in_sizes[1] / F;
    const int M = in_sizes[0] / D;

    __nv_bfloat16* bb;
    float* C1;
    cudaGetSymbolAddress((void**)&bb, g_bf);
    cudaGetSymbolAddress((void**)&C1, g_c1);

    __nv_bfloat16 *xh = bb,            *xl = bb + MDE;
    __nv_bfloat16 *wuh = bb + 2 * MDE, *wul = bb + 3 * MDE;
    __nv_bfloat16 *wgh = bb + 4 * MDE, *wgl = bb + 5 * MDE;
    __nv_bfloat16 *wdh = bb + 6 * MDE, *wdl = bb + 7 * MDE;
    __nv_bfloat16* hb = bb + 8 * MDE;
    __nv_bfloat16 *h1h = hb,           *h1l = hb + FFE;
    __nv_bfloat16 *h2h = hb + 2 * FFE, *h2l = hb + 3 * FFE;
    __nv_bfloat16 *h3h = hb + 4 * FFE, *h3l = hb + 5 * FFE;
    __nv_bfloat16 *Uh = hb + 6 * FFE,  *Ul = hb + 7 * FFE;
    __nv_bfloat16 *Gh = hb + 8 * FFE,  *Gl = hb + 9 * FFE;

    const int nMD4 = (M * D) / 4, nFD4 = (F * D) / 4;
    split_k<<<2048, 256>>>((const float4*)x,  (bf4*)xh,  (bf4*)xl,  nMD4);
    split_k<<<2048, 256>>>((const float4*)wu, (bf4*)wuh, (bf4*)wul, nFD4);
    split_k<<<2048, 256>>>((const float4*)wg, (bf4*)wgh, (bf4*)wgl, nFD4);
    split_k<<<2048, 256>>>((const float4*)wd, (bf4*)wdh, (bf4*)wdl, nFD4);
    const dim3 tg(F / 32, F / 32), tb(32, 8);
    tsplit_k<<<tg, tb>>>(h1, h1h, h1l, F);
    tsplit_k<<<tg, tb>>>(h2, h2h, h2l, F);
    tsplit_k<<<tg, tb>>>(h3, h3h, h3l, F);

    // 1) up   = x @ w_up^T            -> split U
    rung(0, xh, xl, wuh, wul, nullptr, Uh, Ul, nullptr, M, F, D);
    // 2) gate = x @ w_gate^T          -> split G
    rung(0, xh, xl, wgh, wgl, nullptr, Gh, Gl, nullptr, M, F, D);
    // 3) up2  = U @ h_up_T            -> C1 (fp32)
    rung(1, Uh, Ul, h1h, h1l, C1, nullptr, nullptr, nullptr, M, F, F);
    // 4) gated = C1 * silu(G @ h_gate_T) -> split U (reuse)
    rung(2, Gh, Gl, h2h, h2l, nullptr, Uh, Ul, C1, M, F, F);
    // 5) g3   = gated @ h_down        -> split G (reuse)
    rung(0, Uh, Ul, h3h, h3l, nullptr, Gh, Gl, nullptr, M, F, F);
    // 6) out  = g3 @ w_down^T         -> d_out (fp32)
    rung(1, Gh, Gl, wdh, wdl, (float*)d_out, nullptr, nullptr, nullptr, M, D, F);
}

// round 5
// speedup vs baseline: 3.2711x; 1.0286x over previous
#include <cuda_runtime.h>
#include <cuda_bf16.h>
#include <math.h>
#include <stdint.h>

// ===========================================================================
// bf16x3 split GEMM via legacy mma.sync (compute_103-safe: no tcgen05).
// C[M,N] = A[M,K] @ B[N,K]^T with A,B pre-split into (bf16 hi, bf16 lo).
// acc = Ah*Bh + Ah*Bl + Al*Bh  (fp32 accumulators).
// R4: 2 CTAs/SM (launch_bounds 256,2), reduced frag liveness, L2 raster swizzle.
// ===========================================================================

#define TILE_B 8192              // one 128x32 bf16 tile in smem (bytes)
#define STAGE_B 32768            // 4 tiles (Ah,Al,Bh,Bl)
#define SMEM_B3 98304            // 3 stages

__device__ __forceinline__ uint32_t smem_u32(const void* p) {
    uint32_t a;
    asm("{ .reg .u64 t; cvta.to.shared.u64 t, %1; cvt.u32.u64 %0, t; }" : "=r"(a) : "l"(p));
    return a;
}
__device__ __forceinline__ void cp16(uint32_t s, const void* g) {
    asm volatile("cp.async.cg.shared.global [%0], [%1], 16;" :: "r"(s), "l"(g));
}
#define CP_COMMIT() asm volatile("cp.async.commit_group;" ::: "memory")
#define CP_WAIT1()  asm volatile("cp.async.wait_group 1;" ::: "memory")
#define LDSM4(R, a) \
    asm volatile("ldmatrix.sync.aligned.m8n8.x4.shared.b16 {%0,%1,%2,%3}, [%4];" \
        : "=r"((R)[0]), "=r"((R)[1]), "=r"((R)[2]), "=r"((R)[3]) : "r"(a))

__device__ __forceinline__ void mma_bf16(float* c, const uint32_t* a, uint32_t b0, uint32_t b1) {
    asm volatile(
        "mma.sync.aligned.m16n8k16.row.col.f32.bf16.bf16.f32 "
        "{%0,%1,%2,%3}, {%4,%5,%6,%7}, {%8,%9}, {%0,%1,%2,%3};"
        : "+f"(c[0]), "+f"(c[1]), "+f"(c[2]), "+f"(c[3])
        : "r"(a[0]), "r"(a[1]), "r"(a[2]), "r"(a[3]), "r"(b0), "r"(b1));
}

// 16B-granular XOR swizzle: (row, col16) -> byte offset within a 128x32 tile.
__device__ __forceinline__ uint32_t sw(int row, int col16) {
    return (uint32_t)(row * 64 + ((col16 ^ ((row >> 1) & 3)) << 4));
}

// load one pipeline stage: 4 tiles, 2 x 16B chunks per thread per tile
__device__ __forceinline__ void ld_stage(
    uint32_t sb, int buf, int t,
    const __nv_bfloat16* __restrict__ Ah, const __nv_bfloat16* __restrict__ Al,
    const __nv_bfloat16* __restrict__ Bh, const __nv_bfloat16* __restrict__ Bl,
    int bm, int bn, int K, int tid)
{
    const int k0 = t * 32;
    const uint32_t stb = sb + (uint32_t)buf * STAGE_B;
#pragma unroll
    for (int i = 0; i < 2; i++) {
        const int c = tid + i * 256;
        const int row = c >> 2, col16 = c & 3;
        const size_t gA = (size_t)(bm + row) * K + k0 + col16 * 8;
        const size_t gB = (size_t)(bn + row) * K + k0 + col16 * 8;
        const uint32_t so = stb + sw(row, col16);
        cp16(so,              Ah + gA);
        cp16(so + TILE_B,     Al + gA);
        cp16(so + 2 * TILE_B, Bh + gB);
        cp16(so + 3 * TILE_B, Bl + gB);
    }
}

// EPI 0: split-write (Ch,Cl bf16).  EPI 1: fp32 write Cf.
// EPI 2: v = OTH * silu(acc), split-write.
template <int EPI>
__global__ __launch_bounds__(256, 2) void gemm_b3(
    const __nv_bfloat16* __restrict__ Ah, const __nv_bfloat16* __restrict__ Al,
    const __nv_bfloat16* __restrict__ Bh, const __nv_bfloat16* __restrict__ Bl,
    float* __restrict__ Cf, __nv_bfloat16* __restrict__ Ch, __nv_bfloat16* __restrict__ Cl,
    const float* __restrict__ OTH, int M, int N, int K)
{
    extern __shared__ char smem[];
    const uint32_t sb = smem_u32(smem);
    const int tid = threadIdx.x;

    // ---- L2-friendly CTA rasterization (GROUP_M = 16) ----
    const int gn = gridDim.x, gm = gridDim.y;
    const int bid = blockIdx.y * gn + blockIdx.x;
    const int npg = 16 * gn;
    const int gid = bid / npg;
    const int fm = gid * 16;
    const int gs = (gm - fm < 16) ? (gm - fm) : 16;
    const int bm = (fm + (bid % gs)) * 128;
    const int bn = ((bid % npg) / gs) * 128;

    const int w = tid >> 5, lane = tid & 31;
    const int wm = (w >> 2) * 64, wn = (w & 3) * 32;
    const int jj = lane >> 3, rr = lane & 7;
    const int aR = (jj & 1) * 8 + rr, aC16 = jj >> 1;   // A: (m0k0)(m8k0)(m0k8)(m8k8)
    const int bR = (jj >> 1) * 8 + rr, bC16 = jj & 1;   // B: (n0k0)(n0k8)(n8k0)(n8k8)

    float c[4][4][4];
#pragma unroll
    for (int mi = 0; mi < 4; mi++)
#pragma unroll
        for (int ni = 0; ni < 4; ni++)
#pragma unroll
            for (int q = 0; q < 4; q++) c[mi][ni][q] = 0.0f;

    const int nst = K / 32;
    ld_stage(sb, 0, 0, Ah, Al, Bh, Bl, bm, bn, K, tid); CP_COMMIT();
    ld_stage(sb, 1, 1, Ah, Al, Bh, Bl, bm, bn, K, tid); CP_COMMIT();

    for (int t = 0; t < nst; t++) {
        CP_WAIT1();
        __syncthreads();
        if (t + 2 < nst)
            ld_stage(sb, (t + 2) % 3, t + 2, Ah, Al, Bh, Bl, bm, bn, K, tid);
        CP_COMMIT();

        const uint32_t stb = sb + (uint32_t)((t % 3) * STAGE_B);
#pragma unroll
        for (int ks = 0; ks < 2; ks++) {
            uint32_t af[4][4], bhf[2][4], blf[2][4];
            // A-hi frags
#pragma unroll
            for (int mi = 0; mi < 4; mi++)
                LDSM4(af[mi], stb + sw(wm + mi * 16 + aR, ks * 2 + aC16));
            // B-hi / B-lo frags
#pragma unroll
            for (int np = 0; np < 2; np++) {
                const uint32_t bd = stb + 2 * TILE_B + sw(wn + np * 16 + bR, ks * 2 + bC16);
                LDSM4(bhf[np], bd);
                LDSM4(blf[np], bd + TILE_B);
            }
            // hh + hl  (Ah*Bh, Ah*Bl)
#pragma unroll
            for (int mi = 0; mi < 4; mi++)
#pragma unroll
                for (int ni = 0; ni < 4; ni++) {
                    const int p = ni >> 1, q = (ni & 1) * 2;
                    mma_bf16(c[mi][ni], af[mi], bhf[p][q], bhf[p][q + 1]);
                    mma_bf16(c[mi][ni], af[mi], blf[p][q], blf[p][q + 1]);
                }
            // A-lo frags overwrite A-hi (reduced liveness)
#pragma unroll
            for (int mi = 0; mi < 4; mi++)
                LDSM4(af[mi], stb + TILE_B + sw(wm + mi * 16 + aR, ks * 2 + aC16));
            // lh  (Al*Bh)
#pragma unroll
            for (int mi = 0; mi < 4; mi++)
#pragma unroll
                for (int ni = 0; ni < 4; ni++) {
                    const int p = ni >> 1, q = (ni & 1) * 2;
                    mma_bf16(c[mi][ni], af[mi], bhf[p][q], bhf[p][q + 1]);
                }
        }
    }

    // ---- epilogue ----
#pragma unroll
    for (int mi = 0; mi < 4; mi++)
#pragma unroll
        for (int ni = 0; ni < 4; ni++) {
            const int r0 = bm + wm + mi * 16 + (lane >> 2);
            const int col = bn + wn + ni * 8 + (lane & 3) * 2;
            const size_t o0 = (size_t)r0 * N + col;
            const size_t o1 = (size_t)(r0 + 8) * N + col;
            float v0 = c[mi][ni][0], v1 = c[mi][ni][1];
            float v2 = c[mi][ni][2], v3 = c[mi][ni][3];
            if (EPI == 2) {
                const float2 u0 = *(const float2*)(OTH + o0);
                const float2 u1 = *(const float2*)(OTH + o1);
                v0 = u0.x * (v0 / (1.0f + expf(-v0)));
                v1 = u0.y * (v1 / (1.0f + expf(-v1)));
                v2 = u1.x * (v2 / (1.0f + expf(-v2)));
                v3 = u1.y * (v3 / (1.0f + expf(-v3)));
            }
            if (EPI == 1) {
                *(float2*)(Cf + o0) = make_float2(v0, v1);
                *(float2*)(Cf + o1) = make_float2(v2, v3);
            } else {
                __nv_bfloat162 hh, ll;
                hh.x = __float2bfloat16(v0); hh.y = __float2bfloat16(v1);
                ll.x = __float2bfloat16(v0 - __bfloat162float(hh.x));
                ll.y = __float2bfloat16(v1 - __bfloat162float(hh.y));
                *(__nv_bfloat162*)(Ch + o0) = hh;
                *(__nv_bfloat162*)(Cl + o0) = ll;
                hh.x = __float2bfloat16(v2); hh.y = __float2bfloat16(v3);
                ll.x = __float2bfloat16(v2 - __bfloat162float(hh.x));
                ll.y = __float2bfloat16(v3 - __bfloat162float(hh.y));
                *(__nv_bfloat162*)(Ch + o1) = hh;
                *(__nv_bfloat162*)(Cl + o1) = ll;
            }
        }
}

// ===========================================================================
// scratch (static; no allocations). bf16 slab 768M elems + fp32 C1.
// ===========================================================================
#define MDE 16777216ll
#define FFE 67108864ll
__device__ __nv_bfloat16 g_bf[805306368];
__device__ float g_c1[67108864];

// ---- pre-pass: fp32 -> (bf16 hi, bf16 lo) ----
struct bf4 { __nv_bfloat162 a, b; };
__global__ void split_k(const float4* __restrict__ in, bf4* __restrict__ hi,
                        bf4* __restrict__ lo, int n4) {
    for (int i = blockIdx.x * blockDim.x + threadIdx.x; i < n4; i += gridDim.x * blockDim.x) {
        const float4 v = in[i];
        bf4 H, L;
        H.a.x = __float2bfloat16(v.x); H.a.y = __float2bfloat16(v.y);
        H.b.x = __float2bfloat16(v.z); H.b.y = __float2bfloat16(v.w);
        L.a.x = __float2bfloat16(v.x - __bfloat162float(H.a.x));
        L.a.y = __float2bfloat16(v.y - __bfloat162float(H.a.y));
        L.b.x = __float2bfloat16(v.z - __bfloat162float(H.b.x));
        L.b.y = __float2bfloat16(v.w - __bfloat162float(H.b.y));
        hi[i] = H; lo[i] = L;
    }
}
// transpose + split: out_{hi,lo}[n*F+k] = split(in[k*F+n])
__global__ void tsplit_k(const float* __restrict__ in, __nv_bfloat16* __restrict__ hi,
                         __nv_bfloat16* __restrict__ lo, int F) {
    __shared__ float t[32][33];
    const int c0 = blockIdx.x * 32, r0 = blockIdx.y * 32;
#pragma unroll
    for (int i = 0; i < 32; i += 8)
        t[threadIdx.y + i][threadIdx.x] = in[(size_t)(r0 + threadIdx.y + i) * F + c0 + threadIdx.x];
    __syncthreads();
#pragma unroll
    for (int i = 0; i < 32; i += 8) {
        const float v = t[threadIdx.x][threadIdx.y + i];
        const __nv_bfloat16 h = __float2bfloat16(v);
        const size_t o = (size_t)(c0 + threadIdx.y + i) * F + r0 + threadIdx.x;
        hi[o] = h;
        lo[o] = __float2bfloat16(v - __bfloat162float(h));
    }
}

// ===========================================================================
static void rung(int epi,
                 const __nv_bfloat16* Ah, const __nv_bfloat16* Al,
                 const __nv_bfloat16* Bh, const __nv_bfloat16* Bl,
                 float* Cf, __nv_bfloat16* Ch, __nv_bfloat16* Cl,
                 const float* OTH, int M, int N, int K)
{
    const dim3 g(N / 128, M / 128), b(256);
    if (epi == 0) {
        cudaFuncSetAttribute(gemm_b3<0>, cudaFuncAttributeMaxDynamicSharedMemorySize, SMEM_B3);
        gemm_b3<0><<<g, b, SMEM_B3>>>(Ah, Al, Bh, Bl, Cf, Ch, Cl, OTH, M, N, K);
    } else if (epi == 1) {
        cudaFuncSetAttribute(gemm_b3<1>, cudaFuncAttributeMaxDynamicSharedMemorySize, SMEM_B3);
        gemm_b3<1><<<g, b, SMEM_B3>>>(Ah, Al, Bh, Bl, Cf, Ch, Cl, OTH, M, N, K);
    } else {
        cudaFuncSetAttribute(gemm_b3<2>, cudaFuncAttributeMaxDynamicSharedMemorySize, SMEM_B3);
        gemm_b3<2><<<g, b, SMEM_B3>>>(Ah, Al, Bh, Bl, Cf, Ch, Cl, OTH, M, N, K);
    }
}

extern "C" void kernel_launch(void* const* d_in, const int* in_sizes, int n_in,
                              void* d_out, int out_size)
{
    const float* x  = (const float*)d_in[0];
    const float* wu = (const float*)d_in[1];
    const float* wg = (const float*)d_in[2];
    const float* wd = (const float*)d_in[3];
    const float* h1 = (const float*)d_in[4];
    const float* h2 = (const float*)d_in[5];
    const float* h3 = (const float*)d_in[6];

    int F = 1;
    while ((long long)(F + 1) * (F + 1) <= (long long)in_sizes[4]) F++;
    const int D = in_sizes[1] / F;
    const int M = in_sizes[0] / D;

    __nv_bfloat16* bb;
    float* C1;
    cudaGetSymbolAddress((void**)&bb, g_bf);
    cudaGetSymbolAddress((void**)&C1, g_c1);

    __nv_bfloat16 *xh = bb,            *xl = bb + MDE;
    __nv_bfloat16 *wuh = bb + 2 * MDE, *wul = bb + 3 * MDE;
    __nv_bfloat16 *wgh = bb + 4 * MDE, *wgl = bb + 5 * MDE;
    __nv_bfloat16 *wdh = bb + 6 * MDE, *wdl = bb + 7 * MDE;
    __nv_bfloat16* hb = bb + 8 * MDE;
    __nv_bfloat16 *h1h = hb,           *h1l = hb + FFE;
    __nv_bfloat16 *h2h = hb + 2 * FFE, *h2l = hb + 3 * FFE;
    __nv_bfloat16 *h3h = hb + 4 * FFE, *h3l = hb + 5 * FFE;
    __nv_bfloat16 *Uh = hb + 6 * FFE,  *Ul = hb + 7 * FFE;
    __nv_bfloat16 *Gh = hb + 8 * FFE,  *Gl = hb + 9 * FFE;

    const int nMD4 = (M * D) / 4, nFD4 = (F * D) / 4;
    split_k<<<2048, 256>>>((const float4*)x,  (bf4*)xh,  (bf4*)xl,  nMD4);
    split_k<<<2048, 256>>>((const float4*)wu, (bf4*)wuh, (bf4*)wul, nFD4);
    split_k<<<2048, 256>>>((const float4*)wg, (bf4*)wgh, (bf4*)wgl, nFD4);
    split_k<<<2048, 256>>>((const float4*)wd, (bf4*)wdh, (bf4*)wdl, nFD4);
    const dim3 tg(F / 32, F / 32), tb(32, 8);
    tsplit_k<<<tg, tb>>>(h1, h1h, h1l, F);
    tsplit_k<<<tg, tb>>>(h2, h2h, h2l, F);
    tsplit_k<<<tg, tb>>>(h3, h3h, h3l, F);

    // 1) up   = x @ w_up^T            -> split U
    rung(0, xh, xl, wuh, wul, nullptr, Uh, Ul, nullptr, M, F, D);
    // 2) gate = x @ w_gate^T          -> split G
    rung(0, xh, xl, wgh, wgl, nullptr, Gh, Gl, nullptr, M, F, D);
    // 3) up2  = U @ h_up_T            -> C1 (fp32)
    rung(1, Uh, Ul, h1h, h1l, C1, nullptr, nullptr, nullptr, M, F, F);
    // 4) gated = C1 * silu(G @ h_gate_T) -> split U (reuse)
    rung(2, Gh, Gl, h2h, h2l, nullptr, Uh, Ul, C1, M, F, F);
    // 5) g3   = gated @ h_down        -> split G (reuse)
    rung(0, Uh, Ul, h3h, h3l, nullptr, Gh, Gl, nullptr, M, F, F);
    // 6) out  = g3 @ w_down^T         -> d_out (fp32)
    rung(1, Gh, Gl, wdh, wdl, (float*)d_out, nullptr, nullptr, nullptr, M, D, F);
}